// round 3
// baseline (speedup 1.0000x reference)
#include <cuda_runtime.h>
#include <cuda_bf16.h>
#include <math.h>

// ---------------------------------------------------------------------------
// Problem constants
// ---------------------------------------------------------------------------
#define BB   2
#define SS   1025
#define DD   1024
#define HH_  16
#define HD_  64
#define PP   1024
#define KR_  32          // routed top-k
#define SCALE_ 0.125f    // HD^-0.5
#define INV_TEMP 10.0f   // 1/0.1

// ---------------------------------------------------------------------------
// Scratch (single __device__ BSS array; no allocations anywhere)
// ---------------------------------------------------------------------------
static const size_t N_XN  = 2050ull * 1024;   // layernorm1 out  [B*S, D]
static const size_t N_QR  = 2048ull * 1024;   // q_r             [B*P, D]
static const size_t N_KR  = 2048ull * 1024;   // k_r
static const size_t N_SC  = 2048ull * 1024;   // scores          [B*P, P]
static const size_t N_QKV = 2050ull * 3072;   // qkv             [B*S, 3D]
static const size_t N_ATT = 2050ull * 1024;   // attn out        [B*S, D]
static const size_t N_HH  = 2050ull * 4096;   // fc1 out
static const size_t N_HN  = 2050ull * 1024;   // layernorm2 out
static const size_t N_LW  = 2048ull * 32;     // clipped log route_w
static const size_t N_RT  = 2048ull * 32;     // routes (int)

static const size_t OFF_XN  = 0;
static const size_t OFF_QR  = OFF_XN  + N_XN;
static const size_t OFF_KR  = OFF_QR  + N_QR;
static const size_t OFF_SC  = OFF_KR  + N_KR;
static const size_t OFF_QKV = OFF_SC  + N_SC;
static const size_t OFF_ATT = OFF_QKV + N_QKV;
static const size_t OFF_HH  = OFF_ATT + N_ATT;
static const size_t OFF_HN  = OFF_HH  + N_HH;
static const size_t OFF_LW  = OFF_HN  + N_HN;
static const size_t OFF_RT  = OFF_LW  + N_LW;
static const size_t SCR_TOTAL = OFF_RT + N_RT;   // 27,414,528 floats (~110 MB)

__device__ float g_scratch[SCR_TOTAL];

// ---------------------------------------------------------------------------
// Block reduction helpers (blockDim.x == 256)
// ---------------------------------------------------------------------------
__device__ __forceinline__ float blockReduceSum(float v, float* sbuf) {
    int lane = threadIdx.x & 31, wid = threadIdx.x >> 5;
    #pragma unroll
    for (int o = 16; o; o >>= 1) v += __shfl_xor_sync(0xffffffffu, v, o);
    if (lane == 0) sbuf[wid] = v;
    __syncthreads();
    if (wid == 0) {
        v = (lane < 8) ? sbuf[lane] : 0.f;
        #pragma unroll
        for (int o = 4; o; o >>= 1) v += __shfl_xor_sync(0xffffffffu, v, o);
        if (lane == 0) sbuf[0] = v;
    }
    __syncthreads();
    float r = sbuf[0];
    __syncthreads();
    return r;
}

__device__ __forceinline__ float blockReduceMax(float v, float* sbuf) {
    int lane = threadIdx.x & 31, wid = threadIdx.x >> 5;
    #pragma unroll
    for (int o = 16; o; o >>= 1) v = fmaxf(v, __shfl_xor_sync(0xffffffffu, v, o));
    if (lane == 0) sbuf[wid] = v;
    __syncthreads();
    if (wid == 0) {
        v = (lane < 8) ? sbuf[lane] : -3.4e38f;
        #pragma unroll
        for (int o = 4; o; o >>= 1) v = fmaxf(v, __shfl_xor_sync(0xffffffffu, v, o));
        if (lane == 0) sbuf[0] = v;
    }
    __syncthreads();
    float r = sbuf[0];
    __syncthreads();
    return r;
}

// ---------------------------------------------------------------------------
// LayerNorm: one block (256 thr) per row of 1024
// ---------------------------------------------------------------------------
__global__ void layernorm_kernel(const float* __restrict__ in,
                                 const float* __restrict__ w,
                                 const float* __restrict__ b,
                                 float* __restrict__ out) {
    __shared__ float red[32];
    int row = blockIdx.x, tid = threadIdx.x;
    const float4* ip = (const float4*)(in + (size_t)row * 1024);
    float4 v = ip[tid];
    float s = v.x + v.y + v.z + v.w;
    float mean = blockReduceSum(s, red) * (1.f / 1024.f);
    float dx = v.x - mean, dy = v.y - mean, dz = v.z - mean, dw = v.w - mean;
    float ss = dx * dx + dy * dy + dz * dz + dw * dw;
    float var = blockReduceSum(ss, red) * (1.f / 1024.f);
    float rstd = rsqrtf(var + 1e-5f);
    float4 wv = ((const float4*)w)[tid];
    float4 bv = ((const float4*)b)[tid];
    float4 o;
    o.x = dx * rstd * wv.x + bv.x;
    o.y = dy * rstd * wv.y + bv.y;
    o.z = dz * rstd * wv.z + bv.z;
    o.w = dw * rstd * wv.w + bv.w;
    ((float4*)(out + (size_t)row * 1024))[tid] = o;
}

// ---------------------------------------------------------------------------
// Row-wise L2 normalization (in-place), rows of 1024
// ---------------------------------------------------------------------------
__global__ void l2norm_kernel(float* __restrict__ buf) {
    __shared__ float red[32];
    int row = blockIdx.x, tid = threadIdx.x;
    float4* p = (float4*)(buf + (size_t)row * 1024);
    float4 v = p[tid];
    float ss = v.x * v.x + v.y * v.y + v.z * v.z + v.w * v.w;
    float tot = blockReduceSum(ss, red);
    float sc = 1.f / fmaxf(sqrtf(tot), 1e-12f);
    v.x *= sc; v.y *= sc; v.z *= sc; v.w *= sc;
    p[tid] = v;
}

// ---------------------------------------------------------------------------
// Generic NT SGEMM: C[M,N] = A[M,K] * W[N,K]^T  (+ epilogue)
// 128x128 block tile, 8x8 per thread, BK=8, 256 threads.
// ---------------------------------------------------------------------------
#define EPI_BIAS        1
#define EPI_BIAS_RESID  2
#define EPI_BIAS_GELU   3
#define EPI_SCORES      4

template <int EPI>
__global__ __launch_bounds__(256, 2) void sgemm_nt(
    const float* __restrict__ A, const float* __restrict__ W,
    const float* __restrict__ bias, const float* __restrict__ extra,
    float* __restrict__ C, int M, int N, int Kd,
    long sA, long sW, long sC) {

    A += (long)blockIdx.z * sA;
    W += (long)blockIdx.z * sW;
    C += (long)blockIdx.z * sC;

    __shared__ float As[8][128];
    __shared__ float Ws[8][128];

    const int tid = threadIdx.x;
    const int bm = blockIdx.y * 128;
    const int bn = blockIdx.x * 128;
    const int rA = tid >> 1;            // 0..127
    const int cA = (tid & 1) << 2;      // 0 or 4
    const int tr = (tid >> 4) << 3;     // thread row base (0..120)
    const int tc = (tid & 15) << 3;     // thread col base

    float acc[8][8];
    #pragma unroll
    for (int i = 0; i < 8; i++)
        #pragma unroll
        for (int j = 0; j < 8; j++) acc[i][j] = 0.f;

    const bool aValid = (bm + rA) < M;
    const float* Aptr = A + (long)(bm + rA) * Kd + cA;
    const float* Wptr = W + (long)(bn + rA) * Kd + cA;

    for (int k0 = 0; k0 < Kd; k0 += 8) {
        float4 av = aValid ? *(const float4*)(Aptr + k0) : make_float4(0.f, 0.f, 0.f, 0.f);
        float4 wv = *(const float4*)(Wptr + k0);
        As[cA + 0][rA] = av.x; As[cA + 1][rA] = av.y;
        As[cA + 2][rA] = av.z; As[cA + 3][rA] = av.w;
        Ws[cA + 0][rA] = wv.x; Ws[cA + 1][rA] = wv.y;
        Ws[cA + 2][rA] = wv.z; Ws[cA + 3][rA] = wv.w;
        __syncthreads();
        #pragma unroll
        for (int kk = 0; kk < 8; kk++) {
            float af[8], wf[8];
            *(float4*)&af[0] = *(const float4*)&As[kk][tr];
            *(float4*)&af[4] = *(const float4*)&As[kk][tr + 4];
            *(float4*)&wf[0] = *(const float4*)&Ws[kk][tc];
            *(float4*)&wf[4] = *(const float4*)&Ws[kk][tc + 4];
            #pragma unroll
            for (int i = 0; i < 8; i++)
                #pragma unroll
                for (int j = 0; j < 8; j++) acc[i][j] += af[i] * wf[j];
        }
        __syncthreads();
    }

    #pragma unroll
    for (int i = 0; i < 8; i++) {
        int m = bm + tr + i;
        if (m >= M) continue;
        #pragma unroll
        for (int j = 0; j < 8; j++) {
            int n = bn + tc + j;
            float v = acc[i][j];
            if (EPI == EPI_BIAS) {
                v += bias[n];
            } else if (EPI == EPI_BIAS_RESID) {
                v += bias[n] + extra[(long)m * N + n];
            } else if (EPI == EPI_BIAS_GELU) {
                v += bias[n];
                v = 0.5f * v * (1.0f + erff(v * 0.70710678118654752f));
            } else if (EPI == EPI_SCORES) {
                v += extra[(long)m * N + n];
                if (m == n) v = -1e9f;
            }
            C[(long)m * N + n] = v;
        }
    }
}

// ---------------------------------------------------------------------------
// Top-K=32 per row of 1024 scores + log-softmax routing weights (clipped).
// One block (256 thr) per (b,p) row. Tie-break: lower index (matches lax.top_k).
// ---------------------------------------------------------------------------
__global__ void topk_kernel(const float* __restrict__ scores,
                            int* __restrict__ routes,
                            float* __restrict__ logw) {
    __shared__ float s[1024];
    __shared__ float selv[32];
    __shared__ int   seli[32];
    __shared__ float rv[8];
    __shared__ int   ri[8];
    int row = blockIdx.x, tid = threadIdx.x;
    int lane = tid & 31, wid = tid >> 5;
    const float* src = scores + (size_t)row * 1024;
    s[tid] = src[tid]; s[tid + 256] = src[tid + 256];
    s[tid + 512] = src[tid + 512]; s[tid + 768] = src[tid + 768];
    __syncthreads();

    for (int it = 0; it < 32; it++) {
        float bv = -3.4e38f; int bi = 0x7fffffff;
        #pragma unroll
        for (int c = 0; c < 4; c++) {
            int idx = tid + c * 256;
            float v = s[idx];
            if (v > bv || (v == bv && idx < bi)) { bv = v; bi = idx; }
        }
        #pragma unroll
        for (int o = 16; o; o >>= 1) {
            float ov = __shfl_xor_sync(0xffffffffu, bv, o);
            int   oi = __shfl_xor_sync(0xffffffffu, bi, o);
            if (ov > bv || (ov == bv && oi < bi)) { bv = ov; bi = oi; }
        }
        if (lane == 0) { rv[wid] = bv; ri[wid] = bi; }
        __syncthreads();
        if (tid == 0) {
            float fv = rv[0]; int fi = ri[0];
            #pragma unroll
            for (int wn = 1; wn < 8; wn++)
                if (rv[wn] > fv || (rv[wn] == fv && ri[wn] < fi)) { fv = rv[wn]; fi = ri[wn]; }
            selv[it] = fv; seli[it] = fi;
            s[fi] = -3.4e38f;
        }
        __syncthreads();
    }

    if (tid < 32) {
        float t = selv[tid] * INV_TEMP;
        float tmax = selv[0] * INV_TEMP;      // selection order is descending
        float e = expf(t - tmax);
        float z = e;
        #pragma unroll
        for (int o = 16; o; o >>= 1) z += __shfl_xor_sync(0xffffffffu, z, o);
        float lw = t - (tmax + logf(z));
        routes[(size_t)row * 32 + tid] = seli[tid];
        logw[(size_t)row * 32 + tid] = fmaxf(lw, -10.f);
    }
}

// ---------------------------------------------------------------------------
// CLS attention: one block per (b,h); full softmax over S=1025 keys.
// ---------------------------------------------------------------------------
__global__ void cls_attn_kernel(const float* __restrict__ qkv,
                                float* __restrict__ attn) {
    __shared__ float q[64];
    __shared__ float sp[SS];
    __shared__ float red[32];
    __shared__ float po[4][64];
    int bh = blockIdx.x, b = bh >> 4, h = bh & 15;
    int tid = threadIdx.x;
    const float* base = qkv + (size_t)b * SS * 3072;
    if (tid < 64) q[tid] = base[h * 64 + tid];       // Q of token 0
    __syncthreads();

    float lmax = -3.4e38f;
    for (int j = tid; j < SS; j += 256) {
        const float* kr = base + (size_t)j * 3072 + 1024 + h * 64;
        float d = 0.f;
        #pragma unroll
        for (int dd = 0; dd < 64; dd++) d += q[dd] * kr[dd];
        d *= SCALE_;
        sp[j] = d;
        lmax = fmaxf(lmax, d);
    }
    float M = blockReduceMax(lmax, red);
    float ls = 0.f;
    for (int j = tid; j < SS; j += 256) {
        float e = expf(sp[j] - M);
        sp[j] = e;
        ls += e;
    }
    float Z = blockReduceSum(ls, red);

    int g = tid >> 6, d = tid & 63;
    float o = 0.f;
    for (int j = g; j < SS; j += 4)
        o += sp[j] * base[(size_t)j * 3072 + 2048 + h * 64 + d];
    po[g][d] = o;
    __syncthreads();
    if (tid < 64) {
        float r = (po[0][tid] + po[1][tid] + po[2][tid] + po[3][tid]) / Z;
        attn[(size_t)b * SS * 1024 + h * 64 + tid] = r;   // sequence position 0
    }
}

// ---------------------------------------------------------------------------
// Routed patch attention: one block per (b,p); loops 16 heads.
// Gather 32 K/V rows into smem, score+softmax over K=32, weighted sum.
// ---------------------------------------------------------------------------
__global__ void patch_attn_kernel(const float* __restrict__ qkv,
                                  const int* __restrict__ routes,
                                  const float* __restrict__ logw,
                                  float* __restrict__ attn) {
    __shared__ float Kg[32][64];
    __shared__ float Vg[32][64];
    __shared__ float q[64];
    __shared__ float sc[32];
    __shared__ int   rt[32];
    __shared__ float lw[32];
    __shared__ float po[4][64];
    int bp = blockIdx.x, b = bp >> 10, p = bp & 1023;
    int tid = threadIdx.x, lane = tid & 31, w = tid >> 5;
    if (tid < 32) {
        rt[tid] = routes[(size_t)bp * 32 + tid];
        lw[tid] = logw[(size_t)bp * 32 + tid];
    }
    __syncthreads();
    const float* base = qkv + (size_t)b * SS * 3072;
    const size_t qoff = (size_t)(p + 1) * 3072;

    for (int h = 0; h < HH_; h++) {
        if (tid < 64) q[tid] = base[qoff + h * 64 + tid];
        for (int e = tid; e < 2048; e += 256) {
            int k = e >> 6, d = e & 63;
            size_t toff = (size_t)(rt[k] + 1) * 3072 + h * 64 + d;
            Kg[k][d] = base[toff + 1024];
            Vg[k][d] = base[toff + 2048];
        }
        __syncthreads();

        for (int kk = w; kk < 32; kk += 8) {
            float part = q[lane] * Kg[kk][lane] + q[lane + 32] * Kg[kk][lane + 32];
            #pragma unroll
            for (int o = 16; o; o >>= 1) part += __shfl_xor_sync(0xffffffffu, part, o);
            if (lane == 0) sc[kk] = part * SCALE_ + lw[kk];
        }
        __syncthreads();

        if (tid < 32) {
            float v = sc[tid], m = v;
            #pragma unroll
            for (int o = 16; o; o >>= 1) m = fmaxf(m, __shfl_xor_sync(0xffffffffu, m, o));
            float e = expf(v - m), z = e;
            #pragma unroll
            for (int o = 16; o; o >>= 1) z += __shfl_xor_sync(0xffffffffu, z, o);
            sc[tid] = e / z;
        }
        __syncthreads();

        int g = tid >> 6, d = tid & 63;
        float o = 0.f;
        #pragma unroll
        for (int kk = g; kk < 32; kk += 4) o += sc[kk] * Vg[kk][d];
        po[g][d] = o;
        __syncthreads();
        if (tid < 64)
            attn[((size_t)b * SS + p + 1) * 1024 + h * 64 + tid] =
                po[0][tid] + po[1][tid] + po[2][tid] + po[3][tid];
        __syncthreads();
    }
}

// ---------------------------------------------------------------------------
// Orchestration
// ---------------------------------------------------------------------------
extern "C" void kernel_launch(void* const* d_in, const int* in_sizes, int n_in,
                              void* d_out, int out_size) {
    const float* x        = (const float*)d_in[0];
    const float* n1w      = (const float*)d_in[1];
    const float* n1b      = (const float*)d_in[2];
    const float* rq_w     = (const float*)d_in[3];
    const float* rq_b     = (const float*)d_in[4];
    const float* rk_w     = (const float*)d_in[5];
    const float* rk_b     = (const float*)d_in[6];
    const float* pos_bias = (const float*)d_in[7];
    const float* qkv_w    = (const float*)d_in[8];
    const float* qkv_b    = (const float*)d_in[9];
    const float* proj_w   = (const float*)d_in[10];
    const float* proj_b   = (const float*)d_in[11];
    const float* n2w      = (const float*)d_in[12];
    const float* n2b      = (const float*)d_in[13];
    const float* fc1_w    = (const float*)d_in[14];
    const float* fc1_b    = (const float*)d_in[15];
    const float* fc2_w    = (const float*)d_in[16];
    const float* fc2_b    = (const float*)d_in[17];
    float* out = (float*)d_out;

    void* sp = nullptr;
    cudaGetSymbolAddress(&sp, g_scratch);
    float* SCR = (float*)sp;
    float* XN  = SCR + OFF_XN;
    float* QR  = SCR + OFF_QR;
    float* KRb = SCR + OFF_KR;
    float* SC  = SCR + OFF_SC;
    float* QKV = SCR + OFF_QKV;
    float* ATT = SCR + OFF_ATT;
    float* HHp = SCR + OFF_HH;
    float* HN  = SCR + OFF_HN;
    float* LW  = SCR + OFF_LW;
    int*   RT  = (int*)(SCR + OFF_RT);

    // 1. LayerNorm 1 over all 2050 tokens
    layernorm_kernel<<<BB * SS, 256>>>(x, n1w, n1b, XN);

    // 2. Routing projections on patch tokens (per batch via z-stride)
    dim3 gR(8, 8, 2);
    sgemm_nt<EPI_BIAS><<<gR, 256>>>(XN + 1024, rq_w, rq_b, nullptr, QR,
                                    1024, 1024, 1024,
                                    (long)SS * DD, 0, (long)PP * DD);
    sgemm_nt<EPI_BIAS><<<gR, 256>>>(XN + 1024, rk_w, rk_b, nullptr, KRb,
                                    1024, 1024, 1024,
                                    (long)SS * DD, 0, (long)PP * DD);

    // 3. L2-normalize q_r and k_r (contiguous -> one launch over 4096 rows)
    l2norm_kernel<<<2 * BB * PP, 256>>>(QR);

    // 4. Routing scores = q_r k_r^T + cantor bias, diag = -1e9
    sgemm_nt<EPI_SCORES><<<gR, 256>>>(QR, KRb, nullptr, pos_bias, SC,
                                      1024, 1024, 1024,
                                      (long)PP * DD, (long)PP * DD, (long)PP * PP);

    // 5. Top-32 + clipped log-softmax routing weights
    topk_kernel<<<BB * PP, 256>>>(SC, RT, LW);

    // 6. QKV projection (all 2050 tokens)
    dim3 gQ(24, 17, 1);
    sgemm_nt<EPI_BIAS><<<gQ, 256>>>(XN, qkv_w, qkv_b, nullptr, QKV,
                                    2050, 3072, 1024, 0, 0, 0);

    // 7. CLS attention (token 0, full keys)
    cls_attn_kernel<<<BB * HH_, 256>>>(QKV, ATT);

    // 8. Routed patch attention (tokens 1..1024)
    patch_attn_kernel<<<BB * PP, 256>>>(QKV, RT, LW, ATT);

    // 9. Output projection + residual -> d_out holds x1
    dim3 gP(8, 17, 1);
    sgemm_nt<EPI_BIAS_RESID><<<gP, 256>>>(ATT, proj_w, proj_b, x, out,
                                          2050, 1024, 1024, 0, 0, 0);

    // 10. LayerNorm 2
    layernorm_kernel<<<BB * SS, 256>>>(out, n2w, n2b, HN);

    // 11. FC1 + exact GELU
    dim3 gF1(32, 17, 1);
    sgemm_nt<EPI_BIAS_GELU><<<gF1, 256>>>(HN, fc1_w, fc1_b, nullptr, HHp,
                                          2050, 4096, 1024, 0, 0, 0);

    // 12. FC2 + residual (reads/writes d_out elementwise, no hazard)
    dim3 gF2(8, 17, 1);
    sgemm_nt<EPI_BIAS_RESID><<<gF2, 256>>>(HHp, fc2_w, fc2_b, out, out,
                                           2050, 1024, 4096, 0, 0, 0);

    (void)in_sizes; (void)n_in; (void)out_size;
}